// round 15
// baseline (speedup 1.0000x reference)
#include <cuda_runtime.h>
#include <math.h>
#include <float.h>

#define BB 4
#define NNp 16384
#define SSp 1024
#define KKp 32
#define CF 64
#define NQ (BB*SSp)
#define PT (NQ*KKp)
#define GROWS 96

typedef unsigned long long ull;
__device__ __forceinline__ ull pk2(float lo, float hi){ ull r; asm("mov.b64 %0,{%1,%2};":"=l"(r):"f"(lo),"f"(hi)); return r; }
__device__ __forceinline__ void upk2(ull v, float& lo, float& hi){ asm("mov.b64 {%0,%1},%2;":"=f"(lo),"=f"(hi):"l"(v)); }
__device__ __forceinline__ ull add2(ull a, ull b){ ull r; asm("add.rn.f32x2 %0,%1,%2;":"=l"(r):"l"(a),"l"(b)); return r; }
__device__ __forceinline__ ull mul2(ull a, ull b){ ull r; asm("mul.rn.f32x2 %0,%1,%2;":"=l"(r):"l"(a),"l"(b)); return r; }
__device__ __forceinline__ ull fma2(ull a, ull b, ull c){ ull r; asm("fma.rn.f32x2 %0,%1,%2,%3;":"=l"(r):"l"(a),"l"(b),"l"(c)); return r; }

__device__ float g_featT[(size_t)BB*NNp*CF];
__device__ float g_in  [(size_t)GROWS*PT];
__device__ float g_loc [(size_t)64*PT];
__device__ float g_feat[(size_t)64*PT];
__device__ float g_y1  [(size_t)64*PT];
__device__ float g_y2  [(size_t)128*PT];
__device__ float g_pool[(size_t)NQ*128];
__device__ float g_newc[NQ*3];
__device__ float g_WlT [16*64];
__device__ float g_WfT [80*64];
__device__ float g_W1T [64*64];
__device__ float g_W2T [64*128];
__device__ float g_WpT [128*256];
__device__ float  g_aff [640];
__device__ double g_sums[2][320];
__device__ int    g_fps [NQ];
__device__ int    g_knn [PT];

__global__ void k_zero() {
    int t = threadIdx.x;
    if (t < 320) { g_sums[0][t] = 0.0; g_sums[1][t] = 0.0; }
}

__global__ void k_prep(const float* __restrict__ Wl0, const float* __restrict__ Wf0,
                       const float* __restrict__ W1,  const float* __restrict__ W2,
                       const float* __restrict__ Wp) {
    int t = blockIdx.x*256 + threadIdx.x;
    if (t < 1024) { int k=t>>6, o=t&63;  g_WlT[t] = (k<6)  ? Wl0[o*6+k]  : 0.f; return; }
    t -= 1024;
    if (t < 5120) { int k=t>>6, o=t&63;  g_WfT[t] = (k<67) ? Wf0[o*67+k] : 0.f; return; }
    t -= 5120;
    if (t < 4096) { int k=t>>6, o=t&63;  g_W1T[t] = W1[o*64+k];  return; }
    t -= 4096;
    if (t < 8192) { int k=t>>7, o=t&127; g_W2T[t] = W2[o*64+k];  return; }
    t -= 8192;
    if (t < 32768){ int k=t>>8, o=t&255; g_WpT[t] = Wp[o*128+k]; return; }
}

__global__ void k_tfeat(const float* __restrict__ f) {
    __shared__ float tl[32][33];
    int b = blockIdx.z, c0 = blockIdx.y*32, n0 = blockIdx.x*32;
    const float* fb = f + (size_t)b*CF*NNp;
#pragma unroll
    for (int i = 0; i < 32; i += 8)
        tl[threadIdx.y+i][threadIdx.x] = fb[(size_t)(c0+threadIdx.y+i)*NNp + n0 + threadIdx.x];
    __syncthreads();
#pragma unroll
    for (int i = 0; i < 32; i += 8)
        g_featT[((size_t)b*NNp + n0+threadIdx.y+i)*CF + c0 + threadIdx.x] = tl[threadIdx.x][threadIdx.y+i];
}

/* FPS: single barrier per step. Per-warp REDUX max (dist>=0 -> uint order),
   candidate lanes find min global index, REDUX min, lane0 claims via ONE
   64-bit shared atomicMax on key=(dist_bits<<32)|~index. Lexicographic max
   == (max dist, min index) == jnp.argmax first-index. Triple-buffered keys;
   reset target's readers/writers are separated by barriers (race-free).
   Distance arithmetic bit-identical to passing R9..R13. */
__global__ __launch_bounds__(1024, 1)
void k_fps(const float* __restrict__ center) {
    extern __shared__ float sm[];
    float* sx = sm; float* sy = sm + NNp; float* sz = sm + 2*NNp;
    __shared__ ull s_key[3];
    int b = blockIdx.x, t = threadIdx.x;
    const float* C = center + (size_t)b*NNp*3;
    for (int i = t; i < NNp; i += 1024) {
        sx[i] = C[i*3+0]; sy[i] = C[i*3+1]; sz[i] = C[i*3+2];
    }
    if (t < 3) s_key[t] = 0ull;
    __syncthreads();

    ull Px[8], Py[8], Pz[8];
#pragma unroll
    for (int jj = 0; jj < 8; jj++) {
        int n0 = (2*jj)*1024 + t, n1 = (2*jj+1)*1024 + t;
        Px[jj] = pk2(sx[n0], sx[n1]);
        Py[jj] = pk2(sy[n0], sy[n1]);
        Pz[jj] = pk2(sz[n0], sz[n1]);
    }
    float dist[16];
#pragma unroll
    for (int j = 0; j < 16; j++) dist[j] = 1e10f;

    int lane = t & 31;
    int winner = 0;
    int cur = 0;
    for (int s = 0; s < SSp; s++) {
        if (t == 0) g_fps[b*SSp + s] = winner;
        float cx = sx[winner], cy = sy[winner], cz = sz[winner];
        ull ncx = pk2(-cx, -cx), ncy = pk2(-cy, -cy), ncz = pk2(-cz, -cz);
        float mm[8];
#pragma unroll
        for (int jj = 0; jj < 8; jj++) {
            ull dx = add2(Px[jj], ncx);
            ull dy = add2(Py[jj], ncy);
            ull dz = add2(Pz[jj], ncz);
            ull dd = mul2(dx, dx);
            dd = fma2(dy, dy, dd);
            dd = fma2(dz, dz, dd);
            float d0, d1; upk2(dd, d0, d1);
            float nd0 = fminf(dist[2*jj],   d0); dist[2*jj]   = nd0;
            float nd1 = fminf(dist[2*jj+1], d1); dist[2*jj+1] = nd1;
            mm[jj] = fmaxf(nd0, nd1);
        }
        float tbest = fmaxf(fmaxf(fmaxf(mm[0], mm[1]), fmaxf(mm[2], mm[3])),
                            fmaxf(fmaxf(mm[4], mm[5]), fmaxf(mm[6], mm[7])));
        unsigned tb = __float_as_uint(tbest);
        unsigned wmax = __reduce_max_sync(0xffffffffu, tb);
        unsigned loc = 0xffffffffu;
        if (tb == wmax) {
            float gv = __uint_as_float(wmax);
#pragma unroll
            for (int j = 15; j >= 0; --j)
                if (dist[j] == gv) loc = (unsigned)(j*1024 + t);
        }
        unsigned widx = __reduce_min_sync(0xffffffffu, loc);
        if (lane == 0)
            atomicMax(&s_key[cur], ((ull)wmax << 32) | (ull)(~widx));
        __syncthreads();
        ull key = s_key[cur];
        winner = (int)(~(unsigned)key);
        int nxt = (cur == 2) ? 0 : cur + 1;
        int rst = (nxt == 2) ? 0 : nxt + 1;   /* (cur+2)%3 */
        if (t == 0) s_key[rst] = 0ull;
        cur = nxt;
    }
}

__global__ void k_gather(const float* __restrict__ center,
                         const float* __restrict__ normal,
                         float* __restrict__ out) {
    int q = blockIdx.x*256 + threadIdx.x;
    if (q >= NQ) return;
    int b = q >> 10;
    int n = g_fps[q];
    size_t s3 = ((size_t)b*NNp + n)*3;
#pragma unroll
    for (int c = 0; c < 3; c++) {
        float vc = center[s3 + c];
        out[q*3 + c] = vc;  g_newc[q*3 + c] = vc;
        out[NQ*3 + q*3 + c] = normal[s3 + c];
    }
}

__global__ __launch_bounds__(128)
void k_knn(const float* __restrict__ center) {
    __shared__ float sD[4][32][12];
    __shared__ int   sI[4][32][12];
    int w = threadIdx.x >> 5, ln = threadIdx.x & 31;
    int q = blockIdx.x*4 + w;
    int b = q >> 10;
    const float* C = center + (size_t)b*NNp*3;
    float qx = g_newc[q*3], qy = g_newc[q*3+1], qz = g_newc[q*3+2];
    float qq = __fmaf_rn(qz, qz, __fmaf_rn(qy, qy, __fmul_rn(qx, qx)));

    float kd[12]; int ki[12];
#pragma unroll
    for (int i = 0; i < 12; i++) { kd[i] = FLT_MAX; ki[i] = 0x7fffffff; }

    for (int i = 0; i < 512; i++) {
        int n = i*32 + ln;
        float px = C[n*3], py = C[n*3+1], pz = C[n*3+2];
        float dot = __fmaf_rn(pz, qz, __fmaf_rn(py, qy, __fmul_rn(px, qx)));
        float pp  = __fmaf_rn(pz, pz, __fmaf_rn(py, py, __fmul_rn(px, px)));
        float d   = __fadd_rn(__fadd_rn(__fmul_rn(-2.0f, dot), qq), pp);
        if (d < kd[11] || (d == kd[11] && n < ki[11])) {
            kd[11] = d; ki[11] = n;
#pragma unroll
            for (int j = 11; j > 0; --j) {
                if (kd[j] < kd[j-1] || (kd[j] == kd[j-1] && ki[j] < ki[j-1])) {
                    float tv = kd[j]; kd[j] = kd[j-1]; kd[j-1] = tv;
                    int   ti = ki[j]; ki[j] = ki[j-1]; ki[j-1] = ti;
                }
            }
        }
    }
#pragma unroll
    for (int i = 0; i < 12; i++) { sD[w][ln][i] = kd[i]; sI[w][ln][i] = ki[i]; }
    __syncwarp();

    int p = 0;
    for (int r = 0; r < 32; r++) {
        float v  = (p < 12) ? sD[w][ln][p] : FLT_MAX;
        int   ci = (p < 12) ? sI[w][ln][p] : 0x7fffffff;
        int   bl = ln;
#pragma unroll
        for (int o = 16; o; o >>= 1) {
            float ov = __shfl_xor_sync(0xffffffffu, v,  o);
            int   oc = __shfl_xor_sync(0xffffffffu, ci, o);
            int   ob = __shfl_xor_sync(0xffffffffu, bl, o);
            if (ov < v || (ov == v && oc < ci)) { v = ov; ci = oc; bl = ob; }
        }
        if (ln == 0) g_knn[q*32 + r] = ci;
        if (ln == bl) p++;
    }
}

__global__ void k_build(const float* __restrict__ center, const float* __restrict__ normal) {
    int p = blockIdx.x*256 + threadIdx.x;
    if (p >= PT) return;
    int q = p >> 5;
    int b = q >> 10;
    int n = g_knn[p];
    size_t s3 = ((size_t)b*NNp + n)*3;
    float dx = __fadd_rn(center[s3+0], -g_newc[q*3+0]);
    float dy = __fadd_rn(center[s3+1], -g_newc[q*3+1]);
    float dz = __fadd_rn(center[s3+2], -g_newc[q*3+2]);
    float rho = sqrtf(__fadd_rn(__fmaf_rn(dz,dz,__fmaf_rn(dy,dy,__fmul_rn(dx,dx))), 1e-10f));
    float zd  = dz / fmaxf(rho, 1e-10f);
    zd = fminf(fmaxf(zd, -1.0f), 1.0f);
    float theta = acosf(zd) / 3.14159274101257324f;
    float gx = dx, gy = dy;
    if (fabsf(gx) < 1e-10f) gx += 1e-10f;
    if (fabsf(gy) < 1e-10f) gy += 1e-10f;
    float phi = atan2f(gy, gx) / 6.28318548202514648f + 0.5f;

    g_in[(size_t)0*PT + p] = dx;
    g_in[(size_t)1*PT + p] = dy;
    g_in[(size_t)2*PT + p] = dz;
    g_in[(size_t)3*PT + p] = rho;
    g_in[(size_t)4*PT + p] = theta;
    g_in[(size_t)5*PT + p] = phi;
    g_in[(size_t)16*PT + p] = normal[s3+0];
    g_in[(size_t)17*PT + p] = normal[s3+1];
    g_in[(size_t)18*PT + p] = normal[s3+2];
    const float* f = g_featT + ((size_t)b*NNp + n)*CF;
#pragma unroll 8
    for (int c = 0; c < CF; c++)
        g_in[(size_t)(19+c)*PT + p] = f[c];
}

template<int COUT>
__global__ void __launch_bounds__(COUT*4)
k_gemm(int wsel) {
    __shared__ __align__(16) float sW[16][COUT];
    __shared__ __align__(16) float sIn[16][128];

    const float *WT, *in0, *in1 = nullptr; float* outp;
    int Ktot, sumBase, mode;
    if (wsel == 0)      { WT = g_WlT; in0 = g_in;                 outp = g_loc;  Ktot = 16; sumBase = 0;   mode = 0; }
    else if (wsel == 1) { WT = g_WfT; in0 = g_in + (size_t)16*PT; outp = g_feat; Ktot = 80; sumBase = 64;  mode = 0; }
    else if (wsel == 2) { WT = g_W1T; in0 = g_loc; in1 = g_feat;  outp = g_y1;   Ktot = 64; sumBase = 128; mode = 1; }
    else                { WT = g_W2T; in0 = g_y1;                 outp = g_y2;   Ktot = 64; sumBase = 192; mode = 2; }

    int t = threadIdx.x, tx = t & 31, ty = t >> 5;
    int c0 = blockIdx.x * 128;
    ull acc2[8][2];
#pragma unroll
    for (int i = 0; i < 8; i++) { acc2[i][0] = 0ull; acc2[i][1] = 0ull; }

    for (int k0 = 0; k0 < Ktot; k0 += 16) {
        for (int e = t; e < 16*COUT; e += COUT*4)
            sW[e/COUT][e%COUT] = WT[(size_t)(k0 + e/COUT)*COUT + (e%COUT)];
        for (int e = t; e < 2048; e += COUT*4) {
            int kk = e >> 7, c = e & 127;
            int k = k0 + kk; size_t p = (size_t)c0 + c;
            float v;
            if (mode == 0) {
                v = in0[(size_t)k*PT + p];
            } else if (mode == 1) {
                float aL = g_aff[k],     bL = g_aff[64+k];
                float aF = g_aff[128+k], bF = g_aff[192+k];
                v = __fmaf_rn(aL, in0[(size_t)k*PT+p], bL) + __fmaf_rn(aF, in1[(size_t)k*PT+p], bF);
                v = fmaxf(v, 0.f);
            } else {
                float a1 = g_aff[256+k], b1 = g_aff[320+k];
                v = fmaxf(__fmaf_rn(a1, in0[(size_t)k*PT+p], b1), 0.f);
            }
            sIn[kk][c] = v;
        }
        __syncthreads();
#pragma unroll
        for (int kk = 0; kk < 16; kk++) {
            const ull* bb2 = (const ull*)&sIn[kk][tx*4];
            ull b0 = bb2[0], b1 = bb2[1];
            const float4* wv = (const float4*)&sW[kk][ty*8];
            float4 w0 = wv[0], w1 = wv[1];
            float ws[8] = { w0.x, w0.y, w0.z, w0.w, w1.x, w1.y, w1.z, w1.w };
#pragma unroll
            for (int rr = 0; rr < 8; rr++) {
                ull w2 = pk2(ws[rr], ws[rr]);
                acc2[rr][0] = fma2(w2, b0, acc2[rr][0]);
                acc2[rr][1] = fma2(w2, b1, acc2[rr][1]);
            }
        }
        __syncthreads();
    }

#pragma unroll
    for (int rr = 0; rr < 8; rr++) {
        int r = ty*8 + rr;
        float4 v;
        upk2(acc2[rr][0], v.x, v.y);
        upk2(acc2[rr][1], v.z, v.w);
        *(float4*)&outp[(size_t)r*PT + c0 + tx*4] = v;
        float s  = v.x + v.y + v.z + v.w;
        float s2 = v.x*v.x + v.y*v.y + v.z*v.z + v.w*v.w;
#pragma unroll
        for (int o = 16; o; o >>= 1) {
            s  += __shfl_down_sync(0xffffffffu, s,  o);
            s2 += __shfl_down_sync(0xffffffffu, s2, o);
        }
        if (tx == 0) {
            atomicAdd(&g_sums[0][sumBase + r], (double)s);
            atomicAdd(&g_sums[1][sumBase + r], (double)s2);
        }
    }
}

__global__ void k_fin(int sumBase, int affA, int affB,
                      const float* __restrict__ g, const float* __restrict__ beta, int n) {
    int c = threadIdx.x;
    if (c >= n) return;
    double m   = g_sums[0][sumBase+c] * (1.0/PT);
    double var = g_sums[1][sumBase+c] * (1.0/PT) - m*m;
    double a = (double)g[c] * rsqrt(var + 1e-5);
    g_aff[affA+c] = (float)a;
    g_aff[affB+c] = (float)((double)beta[c] - a*m);
}

__global__ void k_pool() {
    int t = blockIdx.x*256 + threadIdx.x;
    if (t >= NQ*128) return;
    int c = t & 127, q = t >> 7;
    float a = g_aff[384+c], b = g_aff[512+c];
    const float4* src = (const float4*)(g_y2 + (size_t)c*PT + (size_t)q*32);
    float m = 0.f;
#pragma unroll
    for (int i = 0; i < 8; i++) {
        float4 v = src[i];
        m = fmaxf(m, __fmaf_rn(a, v.x, b));
        m = fmaxf(m, __fmaf_rn(a, v.y, b));
        m = fmaxf(m, __fmaf_rn(a, v.z, b));
        m = fmaxf(m, __fmaf_rn(a, v.w, b));
    }
    g_pool[q*128 + c] = m;
}

__global__ __launch_bounds__(256)
void k_gemmF(const float* __restrict__ bp, float* __restrict__ out) {
    __shared__ float sP[16][68];
    __shared__ float sW[16][64];
    int t = threadIdx.x, tq = t >> 4, tn = t & 15;
    int q0 = blockIdx.x*64, n0 = blockIdx.y*64;
    float acc[4][4];
#pragma unroll
    for (int i = 0; i < 4; i++)
#pragma unroll
        for (int j = 0; j < 4; j++) acc[i][j] = 0.f;

    for (int k0 = 0; k0 < 128; k0 += 16) {
        for (int e = t; e < 1024; e += 256) {
            int qq = e >> 4, kk = e & 15;
            sP[kk][qq] = g_pool[(size_t)(q0+qq)*128 + k0 + kk];
        }
        for (int e = t; e < 1024; e += 256) {
            int kk = e >> 6, nn = e & 63;
            sW[kk][nn] = g_WpT[(size_t)(k0+kk)*256 + n0 + nn];
        }
        __syncthreads();
#pragma unroll
        for (int kk = 0; kk < 16; kk++) {
            float pv[4], wv[4];
#pragma unroll
            for (int i = 0; i < 4; i++) { pv[i] = sP[kk][tq*4+i]; wv[i] = sW[kk][tn*4+i]; }
#pragma unroll
            for (int i = 0; i < 4; i++)
#pragma unroll
                for (int j = 0; j < 4; j++)
                    acc[i][j] = __fmaf_rn(pv[i], wv[j], acc[i][j]);
        }
        __syncthreads();
    }
#pragma unroll
    for (int i = 0; i < 4; i++)
#pragma unroll
        for (int j = 0; j < 4; j++)
            out[24576 + (size_t)(q0 + tq*4 + i)*256 + n0 + tn*4 + j] = acc[i][j] + bp[n0 + tn*4 + j];
}

extern "C" void kernel_launch(void* const* d_in, const int* in_sizes, int n_in,
                              void* d_out, int out_size) {
    const float* center = (const float*)d_in[0];
    const float* normal = (const float*)d_in[1];
    const float* feature= (const float*)d_in[2];
    const float* W_l0   = (const float*)d_in[3];
    const float* g_l0   = (const float*)d_in[5];
    const float* be_l0  = (const float*)d_in[6];
    const float* W_f0   = (const float*)d_in[7];
    const float* g_f0   = (const float*)d_in[9];
    const float* be_f0  = (const float*)d_in[10];
    const float* W1     = (const float*)d_in[11];
    const float* g1     = (const float*)d_in[13];
    const float* be1    = (const float*)d_in[14];
    const float* W2     = (const float*)d_in[15];
    const float* g2     = (const float*)d_in[17];
    const float* be2    = (const float*)d_in[18];
    const float* Wp     = (const float*)d_in[19];
    const float* bp     = (const float*)d_in[20];
    float* out = (float*)d_out;

    cudaFuncSetAttribute(k_fps, cudaFuncAttributeMaxDynamicSharedMemorySize, 3*NNp*4);

    k_zero<<<1, 320>>>();
    k_prep<<<200, 256>>>(W_l0, W_f0, W1, W2, Wp);
    k_tfeat<<<dim3(NNp/32, CF/32, BB), dim3(32, 8)>>>(feature);
    k_fps<<<BB, 1024, 3*NNp*4>>>(center);
    k_gather<<<(NQ+255)/256, 256>>>(center, normal, out);
    k_knn<<<NQ/4, 128>>>(center);
    k_build<<<PT/256, 256>>>(center, normal);
    k_gemm<64><<<PT/128, 256>>>(0);
    k_gemm<64><<<PT/128, 256>>>(1);
    k_fin<<<1, 64>>>(0, 0, 64, g_l0, be_l0, 64);
    k_fin<<<1, 64>>>(64, 128, 192, g_f0, be_f0, 64);
    k_gemm<64><<<PT/128, 256>>>(2);
    k_fin<<<1, 64>>>(128, 256, 320, g1, be1, 64);
    k_gemm<128><<<PT/128, 512>>>(3);
    k_fin<<<1, 128>>>(192, 384, 512, g2, be2, 128);
    k_pool<<<(NQ*128)/256, 256>>>();
    k_gemmF<<<dim3(NQ/64, 4), 256>>>(bp, out);
}

// round 17
// speedup vs baseline: 1.2578x; 1.2578x over previous
#include <cuda_runtime.h>
#include <math.h>
#include <float.h>

#define BB 4
#define NNp 16384
#define SSp 1024
#define KKp 32
#define CF 64
#define NQ (BB*SSp)
#define PT (NQ*KKp)
#define GROWS 96
#define CL 8                 /* cluster size for FPS */
#define TFP 256              /* FPS threads per CTA */
#define PPC (NNp/CL)         /* 2048 points per CTA */

typedef unsigned long long ull;
__device__ __forceinline__ ull pk2(float lo, float hi){ ull r; asm("mov.b64 %0,{%1,%2};":"=l"(r):"f"(lo),"f"(hi)); return r; }
__device__ __forceinline__ void upk2(ull v, float& lo, float& hi){ asm("mov.b64 {%0,%1},%2;":"=f"(lo),"=f"(hi):"l"(v)); }
__device__ __forceinline__ ull add2(ull a, ull b){ ull r; asm("add.rn.f32x2 %0,%1,%2;":"=l"(r):"l"(a),"l"(b)); return r; }
__device__ __forceinline__ ull mul2(ull a, ull b){ ull r; asm("mul.rn.f32x2 %0,%1,%2;":"=l"(r):"l"(a),"l"(b)); return r; }
__device__ __forceinline__ ull fma2(ull a, ull b, ull c){ ull r; asm("fma.rn.f32x2 %0,%1,%2,%3;":"=l"(r):"l"(a),"l"(b),"l"(c)); return r; }
__device__ __forceinline__ unsigned ctarank(){ unsigned r; asm("mov.u32 %0, %%cluster_ctarank;" : "=r"(r)); return r; }
__device__ __forceinline__ void st_cluster_u64(unsigned laddr, unsigned rank, ull v){
    unsigned ra; asm("mapa.shared::cluster.u32 %0, %1, %2;" : "=r"(ra) : "r"(laddr), "r"(rank));
    asm volatile("st.shared::cluster.u64 [%0], %1;" :: "r"(ra), "l"(v) : "memory");
}

__device__ float g_featT[(size_t)BB*NNp*CF];
__device__ float g_in  [(size_t)GROWS*PT];
__device__ float g_loc [(size_t)64*PT];
__device__ float g_feat[(size_t)64*PT];
__device__ float g_y1  [(size_t)64*PT];
__device__ float g_y2  [(size_t)128*PT];
__device__ float g_pool[(size_t)NQ*128];
__device__ float g_newc[NQ*3];
__device__ float g_WlT [16*64];
__device__ float g_WfT [80*64];
__device__ float g_W1T [64*64];
__device__ float g_W2T [64*128];
__device__ float g_WpT [128*256];
__device__ float  g_aff [640];
__device__ double g_sums[2][320];
__device__ int    g_fps [NQ];
__device__ int    g_knn [PT];

__global__ void k_zero() {
    int t = threadIdx.x;
    if (t < 320) { g_sums[0][t] = 0.0; g_sums[1][t] = 0.0; }
}

__global__ void k_prep(const float* __restrict__ Wl0, const float* __restrict__ Wf0,
                       const float* __restrict__ W1,  const float* __restrict__ W2,
                       const float* __restrict__ Wp) {
    int t = blockIdx.x*256 + threadIdx.x;
    if (t < 1024) { int k=t>>6, o=t&63;  g_WlT[t] = (k<6)  ? Wl0[o*6+k]  : 0.f; return; }
    t -= 1024;
    if (t < 5120) { int k=t>>6, o=t&63;  g_WfT[t] = (k<67) ? Wf0[o*67+k] : 0.f; return; }
    t -= 5120;
    if (t < 4096) { int k=t>>6, o=t&63;  g_W1T[t] = W1[o*64+k];  return; }
    t -= 4096;
    if (t < 8192) { int k=t>>7, o=t&127; g_W2T[t] = W2[o*64+k];  return; }
    t -= 8192;
    if (t < 32768){ int k=t>>8, o=t&255; g_WpT[t] = Wp[o*128+k]; return; }
}

__global__ void k_tfeat(const float* __restrict__ f) {
    __shared__ float tl[32][33];
    int b = blockIdx.z, c0 = blockIdx.y*32, n0 = blockIdx.x*32;
    const float* fb = f + (size_t)b*CF*NNp;
#pragma unroll
    for (int i = 0; i < 32; i += 8)
        tl[threadIdx.y+i][threadIdx.x] = fb[(size_t)(c0+threadIdx.y+i)*NNp + n0 + threadIdx.x];
    __syncthreads();
#pragma unroll
    for (int i = 0; i < 32; i += 8)
        g_featT[((size_t)b*NNp + n0+threadIdx.y+i)*CF + c0 + threadIdx.x] = tl[threadIdx.x][threadIdx.y+i];
}

/* FPS, clusterized: 8 CTAs per batch each own 2048 points (dist registers),
   every CTA keeps the FULL coordinate copy in smem for winner lookup.
   Per-point arithmetic bit-identical to passing R9..R13. Cross-CTA combine:
   per-CTA key=(dist_bits<<32)|~global_idx -> per-rank mailbox slots in all
   CTAs (plain DSMEM stores, single writer per slot) -> one cluster barrier ->
   local max-combine. Lexicographic max == first-index argmax. */
__global__ __launch_bounds__(TFP, 1) __cluster_dims__(CL, 1, 1)
void k_fps(const float* __restrict__ center) {
    extern __shared__ float sm[];
    float* sx = sm; float* sy = sm + NNp; float* sz = sm + 2*NNp;
    __shared__ unsigned s_wu[8];
    __shared__ ull s_key[3];
    __shared__ ull s_mail[3][CL];
    int t = threadIdx.x;
    unsigned rank = ctarank();
    int b = blockIdx.x / CL;
    const float* C = center + (size_t)b*NNp*3;
    for (int i = t; i < NNp; i += TFP) {
        sx[i] = C[i*3+0]; sy[i] = C[i*3+1]; sz[i] = C[i*3+2];
    }
    if (t < 3) s_key[t] = 0ull;
    if (t < 3*CL) ((ull*)s_mail)[t] = 0ull;
    __syncthreads();
    /* init must be visible before any remote store arrives */
    asm volatile("barrier.cluster.arrive.aligned;" ::: "memory");
    asm volatile("barrier.cluster.wait.aligned;"   ::: "memory");

    /* pair jj holds local n0=(2jj)*TFP+t (lo), n1=n0+TFP (hi); global = rank*PPC + n */
    ull Px[4], Py[4], Pz[4];
#pragma unroll
    for (int jj = 0; jj < 4; jj++) {
        int n0 = (int)rank*PPC + (2*jj)*TFP + t;
        int n1 = n0 + TFP;
        Px[jj] = pk2(sx[n0], sx[n1]);
        Py[jj] = pk2(sy[n0], sy[n1]);
        Pz[jj] = pk2(sz[n0], sz[n1]);
    }
    float dist[8];
#pragma unroll
    for (int j = 0; j < 8; j++) dist[j] = 1e10f;

    int lane = t & 31, wp = t >> 5;
    int winner = 0;
    int cur = 0;
    for (int s = 0; s < SSp; s++) {
        if (rank == 0 && t == 0) g_fps[b*SSp + s] = winner;
        float cx = sx[winner], cy = sy[winner], cz = sz[winner];
        ull ncx = pk2(-cx, -cx), ncy = pk2(-cy, -cy), ncz = pk2(-cz, -cz);
        float mm[4];
#pragma unroll
        for (int jj = 0; jj < 4; jj++) {
            ull dx = add2(Px[jj], ncx);
            ull dy = add2(Py[jj], ncy);
            ull dz = add2(Pz[jj], ncz);
            ull dd = mul2(dx, dx);
            dd = fma2(dy, dy, dd);
            dd = fma2(dz, dz, dd);
            float d0, d1; upk2(dd, d0, d1);
            float nd0 = fminf(dist[2*jj],   d0); dist[2*jj]   = nd0;
            float nd1 = fminf(dist[2*jj+1], d1); dist[2*jj+1] = nd1;
            mm[jj] = fmaxf(nd0, nd1);
        }
        float tbest = fmaxf(fmaxf(mm[0], mm[1]), fmaxf(mm[2], mm[3]));
        unsigned tb = __float_as_uint(tbest);
        unsigned wmax = __reduce_max_sync(0xffffffffu, tb);
        if (lane == 0) s_wu[wp] = wmax;
        __syncthreads();                                   /* bar A */
        unsigned gb = __reduce_max_sync(0xffffffffu, s_wu[lane & 7]);

        unsigned loc = 0xffffffffu;
        if (tb == gb) {
            float gv = __uint_as_float(gb);
#pragma unroll
            for (int j = 7; j >= 0; --j)
                if (dist[j] == gv) loc = (unsigned)((int)rank*PPC + j*TFP + t);
        }
        unsigned widx = __reduce_min_sync(0xffffffffu, loc);
        if (wmax == gb && lane == 0)
            atomicMax(&s_key[cur], ((ull)gb << 32) | (ull)(~widx));
        __syncthreads();                                   /* bar B */
        if (t == 0) {
            ull key = s_key[cur];
            unsigned la = (unsigned)__cvta_generic_to_shared(&s_mail[cur][rank]);
#pragma unroll
            for (int r = 0; r < CL; r++) st_cluster_u64(la, (unsigned)r, key);
        }
        asm volatile("barrier.cluster.arrive.aligned;" ::: "memory");
        asm volatile("barrier.cluster.wait.aligned;"   ::: "memory");

        ull best = s_mail[cur][0];
#pragma unroll
        for (int r = 1; r < CL; r++) { ull k = s_mail[cur][r]; if (k > best) best = k; }
        winner = (int)(~(unsigned)best);

        int nxt = (cur == 2) ? 0 : cur + 1;
        int rst = (nxt == 2) ? 0 : nxt + 1;                /* (cur+2)%3 */
        if (t == 0) {
            s_key[rst] = 0ull;
#pragma unroll
            for (int r = 0; r < CL; r++) s_mail[rst][r] = 0ull;
        }
        cur = nxt;
    }
}

__global__ void k_gather(const float* __restrict__ center,
                         const float* __restrict__ normal,
                         float* __restrict__ out) {
    int q = blockIdx.x*256 + threadIdx.x;
    if (q >= NQ) return;
    int b = q >> 10;
    int n = g_fps[q];
    size_t s3 = ((size_t)b*NNp + n)*3;
#pragma unroll
    for (int c = 0; c < 3; c++) {
        float vc = center[s3 + c];
        out[q*3 + c] = vc;  g_newc[q*3 + c] = vc;
        out[NQ*3 + q*3 + c] = normal[s3 + c];
    }
}

__global__ __launch_bounds__(128)
void k_knn(const float* __restrict__ center) {
    __shared__ float sD[4][32][12];
    __shared__ int   sI[4][32][12];
    int w = threadIdx.x >> 5, ln = threadIdx.x & 31;
    int q = blockIdx.x*4 + w;
    int b = q >> 10;
    const float* C = center + (size_t)b*NNp*3;
    float qx = g_newc[q*3], qy = g_newc[q*3+1], qz = g_newc[q*3+2];
    float qq = __fmaf_rn(qz, qz, __fmaf_rn(qy, qy, __fmul_rn(qx, qx)));

    float kd[12]; int ki[12];
#pragma unroll
    for (int i = 0; i < 12; i++) { kd[i] = FLT_MAX; ki[i] = 0x7fffffff; }

    for (int i = 0; i < 512; i++) {
        int n = i*32 + ln;
        float px = C[n*3], py = C[n*3+1], pz = C[n*3+2];
        float dot = __fmaf_rn(pz, qz, __fmaf_rn(py, qy, __fmul_rn(px, qx)));
        float pp  = __fmaf_rn(pz, pz, __fmaf_rn(py, py, __fmul_rn(px, px)));
        float d   = __fadd_rn(__fadd_rn(__fmul_rn(-2.0f, dot), qq), pp);
        if (d < kd[11] || (d == kd[11] && n < ki[11])) {
            kd[11] = d; ki[11] = n;
#pragma unroll
            for (int j = 11; j > 0; --j) {
                if (kd[j] < kd[j-1] || (kd[j] == kd[j-1] && ki[j] < ki[j-1])) {
                    float tv = kd[j]; kd[j] = kd[j-1]; kd[j-1] = tv;
                    int   ti = ki[j]; ki[j] = ki[j-1]; ki[j-1] = ti;
                }
            }
        }
    }
#pragma unroll
    for (int i = 0; i < 12; i++) { sD[w][ln][i] = kd[i]; sI[w][ln][i] = ki[i]; }
    __syncwarp();

    int p = 0;
    for (int r = 0; r < 32; r++) {
        float v  = (p < 12) ? sD[w][ln][p] : FLT_MAX;
        int   ci = (p < 12) ? sI[w][ln][p] : 0x7fffffff;
        int   bl = ln;
#pragma unroll
        for (int o = 16; o; o >>= 1) {
            float ov = __shfl_xor_sync(0xffffffffu, v,  o);
            int   oc = __shfl_xor_sync(0xffffffffu, ci, o);
            int   ob = __shfl_xor_sync(0xffffffffu, bl, o);
            if (ov < v || (ov == v && oc < ci)) { v = ov; ci = oc; bl = ob; }
        }
        if (ln == 0) g_knn[q*32 + r] = ci;
        if (ln == bl) p++;
    }
}

__global__ void k_build(const float* __restrict__ center, const float* __restrict__ normal) {
    int p = blockIdx.x*256 + threadIdx.x;
    if (p >= PT) return;
    int q = p >> 5;
    int b = q >> 10;
    int n = g_knn[p];
    size_t s3 = ((size_t)b*NNp + n)*3;
    float dx = __fadd_rn(center[s3+0], -g_newc[q*3+0]);
    float dy = __fadd_rn(center[s3+1], -g_newc[q*3+1]);
    float dz = __fadd_rn(center[s3+2], -g_newc[q*3+2]);
    float rho = sqrtf(__fadd_rn(__fmaf_rn(dz,dz,__fmaf_rn(dy,dy,__fmul_rn(dx,dx))), 1e-10f));
    float zd  = dz / fmaxf(rho, 1e-10f);
    zd = fminf(fmaxf(zd, -1.0f), 1.0f);
    float theta = acosf(zd) / 3.14159274101257324f;
    float gx = dx, gy = dy;
    if (fabsf(gx) < 1e-10f) gx += 1e-10f;
    if (fabsf(gy) < 1e-10f) gy += 1e-10f;
    float phi = atan2f(gy, gx) / 6.28318548202514648f + 0.5f;

    g_in[(size_t)0*PT + p] = dx;
    g_in[(size_t)1*PT + p] = dy;
    g_in[(size_t)2*PT + p] = dz;
    g_in[(size_t)3*PT + p] = rho;
    g_in[(size_t)4*PT + p] = theta;
    g_in[(size_t)5*PT + p] = phi;
    g_in[(size_t)16*PT + p] = normal[s3+0];
    g_in[(size_t)17*PT + p] = normal[s3+1];
    g_in[(size_t)18*PT + p] = normal[s3+2];
    const float* f = g_featT + ((size_t)b*NNp + n)*CF;
#pragma unroll 8
    for (int c = 0; c < CF; c++)
        g_in[(size_t)(19+c)*PT + p] = f[c];
}

template<int COUT>
__global__ void __launch_bounds__(COUT*4)
k_gemm(int wsel) {
    __shared__ __align__(16) float sW[16][COUT];
    __shared__ __align__(16) float sIn[16][128];

    const float *WT, *in0, *in1 = nullptr; float* outp;
    int Ktot, sumBase, mode;
    if (wsel == 0)      { WT = g_WlT; in0 = g_in;                 outp = g_loc;  Ktot = 16; sumBase = 0;   mode = 0; }
    else if (wsel == 1) { WT = g_WfT; in0 = g_in + (size_t)16*PT; outp = g_feat; Ktot = 80; sumBase = 64;  mode = 0; }
    else if (wsel == 2) { WT = g_W1T; in0 = g_loc; in1 = g_feat;  outp = g_y1;   Ktot = 64; sumBase = 128; mode = 1; }
    else                { WT = g_W2T; in0 = g_y1;                 outp = g_y2;   Ktot = 64; sumBase = 192; mode = 2; }

    int t = threadIdx.x, tx = t & 31, ty = t >> 5;
    int c0 = blockIdx.x * 128;
    ull acc2[8][2];
#pragma unroll
    for (int i = 0; i < 8; i++) { acc2[i][0] = 0ull; acc2[i][1] = 0ull; }

    for (int k0 = 0; k0 < Ktot; k0 += 16) {
        for (int e = t; e < 16*COUT; e += COUT*4)
            sW[e/COUT][e%COUT] = WT[(size_t)(k0 + e/COUT)*COUT + (e%COUT)];
        for (int e = t; e < 2048; e += COUT*4) {
            int kk = e >> 7, c = e & 127;
            int k = k0 + kk; size_t p = (size_t)c0 + c;
            float v;
            if (mode == 0) {
                v = in0[(size_t)k*PT + p];
            } else if (mode == 1) {
                float aL = g_aff[k],     bL = g_aff[64+k];
                float aF = g_aff[128+k], bF = g_aff[192+k];
                v = __fmaf_rn(aL, in0[(size_t)k*PT+p], bL) + __fmaf_rn(aF, in1[(size_t)k*PT+p], bF);
                v = fmaxf(v, 0.f);
            } else {
                float a1 = g_aff[256+k], b1 = g_aff[320+k];
                v = fmaxf(__fmaf_rn(a1, in0[(size_t)k*PT+p], b1), 0.f);
            }
            sIn[kk][c] = v;
        }
        __syncthreads();
#pragma unroll
        for (int kk = 0; kk < 16; kk++) {
            const ull* bb2 = (const ull*)&sIn[kk][tx*4];
            ull b0 = bb2[0], b1 = bb2[1];
            const float4* wv = (const float4*)&sW[kk][ty*8];
            float4 w0 = wv[0], w1 = wv[1];
            float ws[8] = { w0.x, w0.y, w0.z, w0.w, w1.x, w1.y, w1.z, w1.w };
#pragma unroll
            for (int rr = 0; rr < 8; rr++) {
                ull w2 = pk2(ws[rr], ws[rr]);
                acc2[rr][0] = fma2(w2, b0, acc2[rr][0]);
                acc2[rr][1] = fma2(w2, b1, acc2[rr][1]);
            }
        }
        __syncthreads();
    }

#pragma unroll
    for (int rr = 0; rr < 8; rr++) {
        int r = ty*8 + rr;
        float4 v;
        upk2(acc2[rr][0], v.x, v.y);
        upk2(acc2[rr][1], v.z, v.w);
        *(float4*)&outp[(size_t)r*PT + c0 + tx*4] = v;
        float s  = v.x + v.y + v.z + v.w;
        float s2 = v.x*v.x + v.y*v.y + v.z*v.z + v.w*v.w;
#pragma unroll
        for (int o = 16; o; o >>= 1) {
            s  += __shfl_down_sync(0xffffffffu, s,  o);
            s2 += __shfl_down_sync(0xffffffffu, s2, o);
        }
        if (tx == 0) {
            atomicAdd(&g_sums[0][sumBase + r], (double)s);
            atomicAdd(&g_sums[1][sumBase + r], (double)s2);
        }
    }
}

__global__ void k_fin(int sumBase, int affA, int affB,
                      const float* __restrict__ g, const float* __restrict__ beta, int n) {
    int c = threadIdx.x;
    if (c >= n) return;
    double m   = g_sums[0][sumBase+c] * (1.0/PT);
    double var = g_sums[1][sumBase+c] * (1.0/PT) - m*m;
    double a = (double)g[c] * rsqrt(var + 1e-5);
    g_aff[affA+c] = (float)a;
    g_aff[affB+c] = (float)((double)beta[c] - a*m);
}

__global__ void k_pool() {
    int t = blockIdx.x*256 + threadIdx.x;
    if (t >= NQ*128) return;
    int c = t & 127, q = t >> 7;
    float a = g_aff[384+c], b = g_aff[512+c];
    const float4* src = (const float4*)(g_y2 + (size_t)c*PT + (size_t)q*32);
    float m = 0.f;
#pragma unroll
    for (int i = 0; i < 8; i++) {
        float4 v = src[i];
        m = fmaxf(m, __fmaf_rn(a, v.x, b));
        m = fmaxf(m, __fmaf_rn(a, v.y, b));
        m = fmaxf(m, __fmaf_rn(a, v.z, b));
        m = fmaxf(m, __fmaf_rn(a, v.w, b));
    }
    g_pool[q*128 + c] = m;
}

__global__ __launch_bounds__(256)
void k_gemmF(const float* __restrict__ bp, float* __restrict__ out) {
    __shared__ float sP[16][68];
    __shared__ float sW[16][64];
    int t = threadIdx.x, tq = t >> 4, tn = t & 15;
    int q0 = blockIdx.x*64, n0 = blockIdx.y*64;
    float acc[4][4];
#pragma unroll
    for (int i = 0; i < 4; i++)
#pragma unroll
        for (int j = 0; j < 4; j++) acc[i][j] = 0.f;

    for (int k0 = 0; k0 < 128; k0 += 16) {
        for (int e = t; e < 1024; e += 256) {
            int qq = e >> 4, kk = e & 15;
            sP[kk][qq] = g_pool[(size_t)(q0+qq)*128 + k0 + kk];
        }
        for (int e = t; e < 1024; e += 256) {
            int kk = e >> 6, nn = e & 63;
            sW[kk][nn] = g_WpT[(size_t)(k0+kk)*256 + n0 + nn];
        }
        __syncthreads();
#pragma unroll
        for (int kk = 0; kk < 16; kk++) {
            float pv[4], wv[4];
#pragma unroll
            for (int i = 0; i < 4; i++) { pv[i] = sP[kk][tq*4+i]; wv[i] = sW[kk][tn*4+i]; }
#pragma unroll
            for (int i = 0; i < 4; i++)
#pragma unroll
                for (int j = 0; j < 4; j++)
                    acc[i][j] = __fmaf_rn(pv[i], wv[j], acc[i][j]);
        }
        __syncthreads();
    }
#pragma unroll
    for (int i = 0; i < 4; i++)
#pragma unroll
        for (int j = 0; j < 4; j++)
            out[24576 + (size_t)(q0 + tq*4 + i)*256 + n0 + tn*4 + j] = acc[i][j] + bp[n0 + tn*4 + j];
}

extern "C" void kernel_launch(void* const* d_in, const int* in_sizes, int n_in,
                              void* d_out, int out_size) {
    const float* center = (const float*)d_in[0];
    const float* normal = (const float*)d_in[1];
    const float* feature= (const float*)d_in[2];
    const float* W_l0   = (const float*)d_in[3];
    const float* g_l0   = (const float*)d_in[5];
    const float* be_l0  = (const float*)d_in[6];
    const float* W_f0   = (const float*)d_in[7];
    const float* g_f0   = (const float*)d_in[9];
    const float* be_f0  = (const float*)d_in[10];
    const float* W1     = (const float*)d_in[11];
    const float* g1     = (const float*)d_in[13];
    const float* be1    = (const float*)d_in[14];
    const float* W2     = (const float*)d_in[15];
    const float* g2     = (const float*)d_in[17];
    const float* be2    = (const float*)d_in[18];
    const float* Wp     = (const float*)d_in[19];
    const float* bp     = (const float*)d_in[20];
    float* out = (float*)d_out;

    cudaFuncSetAttribute(k_fps, cudaFuncAttributeMaxDynamicSharedMemorySize, 3*NNp*4);

    k_zero<<<1, 320>>>();
    k_prep<<<200, 256>>>(W_l0, W_f0, W1, W2, Wp);
    k_tfeat<<<dim3(NNp/32, CF/32, BB), dim3(32, 8)>>>(feature);
    k_fps<<<BB*CL, TFP, 3*NNp*4>>>(center);
    k_gather<<<(NQ+255)/256, 256>>>(center, normal, out);
    k_knn<<<NQ/4, 128>>>(center);
    k_build<<<PT/256, 256>>>(center, normal);
    k_gemm<64><<<PT/128, 256>>>(0);
    k_gemm<64><<<PT/128, 256>>>(1);
    k_fin<<<1, 64>>>(0, 0, 64, g_l0, be_l0, 64);
    k_fin<<<1, 64>>>(64, 128, 192, g_f0, be_f0, 64);
    k_gemm<64><<<PT/128, 256>>>(2);
    k_fin<<<1, 64>>>(128, 256, 320, g1, be1, 64);
    k_gemm<128><<<PT/128, 512>>>(3);
    k_fin<<<1, 128>>>(192, 384, 512, g2, be2, 128);
    k_pool<<<(NQ*128)/256, 256>>>();
    k_gemmF<<<dim3(NQ/64, 4), 256>>>(bp, out);
}